// round 1
// baseline (speedup 1.0000x reference)
#include <cuda_runtime.h>

// ---------------------------------------------------------------------------
// Problem constants
// ---------------------------------------------------------------------------
#define BB   2
#define LL   1024            // query length
#define KVL  2048            // kv length (LP + L)
#define DD   2048            // model dim
#define DLAT 1024            // latent dim
#define NH   16
#define DHd  64

// Output region offsets (floats), tuple order: out, z_all, key_rope_all, attn_weights, scores
#define OUT_OUT    0L
#define OUT_ZALL   4194304L     // 2*1024*2048
#define OUT_KRA    8388608L     // + 2*2048*1024
#define OUT_ATTN   12582912L    // + 2*2048*1024
#define OUT_SCORES 79691776L    // + 2*16*1024*2048

// ---------------------------------------------------------------------------
// Scratch (static device allocations; no cudaMalloc allowed)
// ---------------------------------------------------------------------------
__device__ float g_qlat   [2048 * 1024];
__device__ float g_qx     [2048 * 1024];
__device__ float g_query  [2048 * 1024];
__device__ float g_qrope  [2048 * 1024];
__device__ float g_kx     [2048 * 1024];
__device__ float g_keyc   [2 * 2048 * 1024];
__device__ float g_value  [2 * 2048 * 1024];
__device__ float g_qfull  [2 * 16 * 1024 * 128];
__device__ float g_kfull  [2 * 16 * 2048 * 128];
__device__ float g_headout[2048 * 1024];
__device__ float g_probs  [67108864];   // 2*16*1024*2048

// ---------------------------------------------------------------------------
// Generic batched SGEMM, NN variant.  C = alpha * A@B + bias
// Tile: 128(M) x 64(N), K-step 16, 256 threads, 8x4 per-thread microtile.
// Batch offsets: z1 = z/HD, z2 = z%HD;  off = z1*s1 + z2*s2  (per operand).
// All of M%128, N%64, K%16 are 0 for every call in this problem.
// ---------------------------------------------------------------------------
__global__ void __launch_bounds__(256) gemm_nn_kernel(
    const float* __restrict__ A, const float* __restrict__ Bm,
    const float* __restrict__ bias, float* __restrict__ C,
    int M, int N, int K, int lda, int ldb, int ldc,
    int HD, long sA1, long sA2, long sB1, long sB2, long sC1, long sC2,
    float alpha)
{
    __shared__ float As[16][128];
    __shared__ float Bs[16][64];

    int z  = blockIdx.z;
    int z1 = z / HD, z2 = z % HD;
    const float* Ab = A  + (long)z1 * sA1 + (long)z2 * sA2 + (long)blockIdx.y * 128 * lda;
    const float* Bb = Bm + (long)z1 * sB1 + (long)z2 * sB2 + (long)blockIdx.x * 64;
    float*       Cb = C  + (long)z1 * sC1 + (long)z2 * sC2
                         + (long)blockIdx.y * 128 * ldc + (long)blockIdx.x * 64;

    int tid = threadIdx.x;
    int am = tid >> 1;            // 0..127
    int ak = (tid & 1) << 3;      // 0 or 8
    int bk = tid >> 4;            // 0..15
    int bn = (tid & 15) << 2;     // 0..60
    int tm = (tid >> 4) << 3;     // 0..120
    int tn = (tid & 15) << 2;     // 0..60

    float acc[8][4];
    #pragma unroll
    for (int i = 0; i < 8; i++)
        #pragma unroll
        for (int j = 0; j < 4; j++) acc[i][j] = 0.f;

    for (int kt = 0; kt < K; kt += 16) {
        float4 a0 = *(const float4*)(Ab + (long)am * lda + kt + ak);
        float4 a1 = *(const float4*)(Ab + (long)am * lda + kt + ak + 4);
        As[ak + 0][am] = a0.x; As[ak + 1][am] = a0.y;
        As[ak + 2][am] = a0.z; As[ak + 3][am] = a0.w;
        As[ak + 4][am] = a1.x; As[ak + 5][am] = a1.y;
        As[ak + 6][am] = a1.z; As[ak + 7][am] = a1.w;
        *(float4*)(&Bs[bk][bn]) = *(const float4*)(Bb + (long)(kt + bk) * ldb + bn);
        __syncthreads();

        #pragma unroll
        for (int k = 0; k < 16; k++) {
            float ar[8], br[4];
            *(float4*)(ar)     = *(const float4*)(&As[k][tm]);
            *(float4*)(ar + 4) = *(const float4*)(&As[k][tm + 4]);
            *(float4*)(br)     = *(const float4*)(&Bs[k][tn]);
            #pragma unroll
            for (int i = 0; i < 8; i++)
                #pragma unroll
                for (int j = 0; j < 4; j++)
                    acc[i][j] += ar[i] * br[j];
        }
        __syncthreads();
    }

    float bv[4] = {0.f, 0.f, 0.f, 0.f};
    if (bias) {
        #pragma unroll
        for (int j = 0; j < 4; j++) bv[j] = bias[blockIdx.x * 64 + tn + j];
    }
    #pragma unroll
    for (int i = 0; i < 8; i++) {
        float4 o;
        o.x = acc[i][0] * alpha + bv[0];
        o.y = acc[i][1] * alpha + bv[1];
        o.z = acc[i][2] * alpha + bv[2];
        o.w = acc[i][3] * alpha + bv[3];
        *(float4*)(Cb + (long)(tm + i) * ldc + tn) = o;
    }
}

// NT variant: C = alpha * A @ B^T, B is (N x K) row-major.
__global__ void __launch_bounds__(256) gemm_nt_kernel(
    const float* __restrict__ A, const float* __restrict__ Bm,
    float* __restrict__ C,
    int M, int N, int K, int lda, int ldb, int ldc,
    long sA1, long sB1, long sC1, float alpha)
{
    __shared__ float As[16][128];
    __shared__ float Bs[16][64];

    int z = blockIdx.z;
    const float* Ab = A  + (long)z * sA1 + (long)blockIdx.y * 128 * lda;
    const float* Bb = Bm + (long)z * sB1 + (long)blockIdx.x * 64 * ldb;
    float*       Cb = C  + (long)z * sC1 + (long)blockIdx.y * 128 * ldc + (long)blockIdx.x * 64;

    int tid = threadIdx.x;
    int am = tid >> 1;            // 0..127
    int ak = (tid & 1) << 3;      // 0 or 8
    int bn2 = tid >> 2;           // 0..63
    int bk2 = (tid & 3) << 2;     // 0,4,8,12
    int tm = (tid >> 4) << 3;
    int tn = (tid & 15) << 2;

    float acc[8][4];
    #pragma unroll
    for (int i = 0; i < 8; i++)
        #pragma unroll
        for (int j = 0; j < 4; j++) acc[i][j] = 0.f;

    for (int kt = 0; kt < K; kt += 16) {
        float4 a0 = *(const float4*)(Ab + (long)am * lda + kt + ak);
        float4 a1 = *(const float4*)(Ab + (long)am * lda + kt + ak + 4);
        As[ak + 0][am] = a0.x; As[ak + 1][am] = a0.y;
        As[ak + 2][am] = a0.z; As[ak + 3][am] = a0.w;
        As[ak + 4][am] = a1.x; As[ak + 5][am] = a1.y;
        As[ak + 6][am] = a1.z; As[ak + 7][am] = a1.w;
        float4 b0 = *(const float4*)(Bb + (long)bn2 * ldb + kt + bk2);
        Bs[bk2 + 0][bn2] = b0.x; Bs[bk2 + 1][bn2] = b0.y;
        Bs[bk2 + 2][bn2] = b0.z; Bs[bk2 + 3][bn2] = b0.w;
        __syncthreads();

        #pragma unroll
        for (int k = 0; k < 16; k++) {
            float ar[8], br[4];
            *(float4*)(ar)     = *(const float4*)(&As[k][tm]);
            *(float4*)(ar + 4) = *(const float4*)(&As[k][tm + 4]);
            *(float4*)(br)     = *(const float4*)(&Bs[k][tn]);
            #pragma unroll
            for (int i = 0; i < 8; i++)
                #pragma unroll
                for (int j = 0; j < 4; j++)
                    acc[i][j] += ar[i] * br[j];
        }
        __syncthreads();
    }

    #pragma unroll
    for (int i = 0; i < 8; i++) {
        float4 o;
        o.x = acc[i][0] * alpha;
        o.y = acc[i][1] * alpha;
        o.z = acc[i][2] * alpha;
        o.w = acc[i][3] * alpha;
        *(float4*)(Cb + (long)(tm + i) * ldc + tn) = o;
    }
}

// ---------------------------------------------------------------------------
// Elementwise helpers
// ---------------------------------------------------------------------------

// Copy a (B, 1024, 1024) tensor into the first 1024 rows of a (B, 2048, 1024) tensor.
__global__ void copy_concat_kernel(const float* __restrict__ src, float* __restrict__ dst)
{
    long i = (long)blockIdx.x * 256 + threadIdx.x;   // total 2*1024*1024
    if (i >= 2L * 1024 * 1024) return;
    long r = i >> 10, c = i & 1023;
    long b = r >> 10, l = r & 1023;
    dst[((b * 2048) + l) * 1024 + c] = src[i];
}

// Rotary embedding over (2048 rows, 16 heads, 64 dims); pos = row % 1024.
// mode 0: dst row == src row (q path).  mode 1: dst row = b*2048 + 1024 + l (k path into key_rope_all).
__global__ void rotary_kernel(const float* __restrict__ src, float* __restrict__ dst, int mode)
{
    int idx = blockIdx.x * 256 + threadIdx.x;        // total 2048*16*32
    if (idx >= 2048 * 16 * 32) return;
    int i = idx & 31;
    int h = (idx >> 5) & 15;
    int r = idx >> 9;
    int pos = r & 1023;
    float fr = expf(-9.2103403719761836f * (float)i / 32.0f);  // 10000^(-i/32)
    float ang = (float)pos * fr;
    float sn, cs;
    sincosf(ang, &sn, &cs);
    const float* s = src + (long)r * 1024 + h * 64 + i;
    float s1 = s[0], s2 = s[32];
    long drow = mode ? ((long)(r >> 10) * 2048 + 1024 + (r & 1023)) : (long)r;
    float* d = dst + drow * 1024 + h * 64 + i;
    d[0]  = s1 * cs - s2 * sn;
    d[32] = s1 * sn + s2 * cs;
}

// qfull[b,h,l,d] with d in [0,128): slice of concat([query, q_rope]) at h*128+d
__global__ void pack_q_kernel(const float* __restrict__ q, const float* __restrict__ qr,
                              float* __restrict__ qf)
{
    long idx = (long)blockIdx.x * 256 + threadIdx.x;  // 2*16*1024*128
    if (idx >= 4194304L) return;
    long d = idx & 127;
    long l = (idx >> 7) & 1023;
    long h = (idx >> 17) & 15;
    long b = idx >> 21;
    long c = h * 128 + d;   // 0..2047 into concat vector
    const float* src = (c < 1024) ? q : qr;
    qf[idx] = src[(b * 1024 + l) * 1024 + (c & 1023)];
}

// kfull[b,h,kv,d]: slice of concat([key_c, key_rope_all]) at h*128+d
__global__ void pack_k_kernel(const float* __restrict__ kc, const float* __restrict__ kra,
                              float* __restrict__ kf)
{
    long idx = (long)blockIdx.x * 256 + threadIdx.x;  // 2*16*2048*128
    if (idx >= 8388608L) return;
    long d  = idx & 127;
    long kv = (idx >> 7) & 2047;
    long h  = (idx >> 18) & 15;
    long b  = idx >> 22;
    long c = h * 128 + d;
    const float* src = (c < 1024) ? kc : kra;
    kf[idx] = src[(b * 2048 + kv) * 1024 + (c & 1023)];
}

// ---------------------------------------------------------------------------
// Dual softmax: one row (b,h,l) of 2048 scores -> attn (unmasked) + probs (masked)
// ---------------------------------------------------------------------------
__global__ void __launch_bounds__(256) softmax_kernel(
    const float* __restrict__ scores, const int* __restrict__ vlens,
    float* __restrict__ attn, float* __restrict__ probs)
{
    int row = blockIdx.x;              // ((b*16 + h)*1024 + l)
    int l = row & 1023;
    int b = row >> 14;
    int vl = vlens[b * 1024 + l];
    const float* s = scores + (long)row * 2048;
    int tid = threadIdx.x;

    float v[8], e2[8];
    float mu = -1e30f, mm = -1e30f;
    #pragma unroll
    for (int i = 0; i < 8; i++) {
        int kv = tid + (i << 8);
        v[i] = s[kv];
        mu = fmaxf(mu, v[i]);
        if (kv < vl) mm = fmaxf(mm, v[i]);
    }
    __shared__ float red[16];
    #pragma unroll
    for (int o = 16; o > 0; o >>= 1) {
        mu = fmaxf(mu, __shfl_xor_sync(0xffffffffu, mu, o));
        mm = fmaxf(mm, __shfl_xor_sync(0xffffffffu, mm, o));
    }
    int w = tid >> 5, lane = tid & 31;
    if (lane == 0) { red[w] = mu; red[w + 8] = mm; }
    __syncthreads();
    mu = -1e30f; mm = -1e30f;
    #pragma unroll
    for (int i = 0; i < 8; i++) { mu = fmaxf(mu, red[i]); mm = fmaxf(mm, red[8 + i]); }
    __syncthreads();

    float su = 0.f, sm = 0.f;
    #pragma unroll
    for (int i = 0; i < 8; i++) {
        int kv = tid + (i << 8);
        float eu = expf(v[i] - mu);
        float em = (kv < vl) ? expf(v[i] - mm) : 0.f;   // exp(-10000 - mm) underflows to 0 in f32
        v[i] = eu; e2[i] = em;
        su += eu; sm += em;
    }
    #pragma unroll
    for (int o = 16; o > 0; o >>= 1) {
        su += __shfl_xor_sync(0xffffffffu, su, o);
        sm += __shfl_xor_sync(0xffffffffu, sm, o);
    }
    if (lane == 0) { red[w] = su; red[w + 8] = sm; }
    __syncthreads();
    su = 0.f; sm = 0.f;
    #pragma unroll
    for (int i = 0; i < 8; i++) { su += red[i]; sm += red[8 + i]; }
    float iu = 1.f / su, im = 1.f / sm;

    float* arow = attn  + (long)row * 2048;
    float* prow = probs + (long)row * 2048;
    #pragma unroll
    for (int i = 0; i < 8; i++) {
        int kv = tid + (i << 8);
        arow[kv] = v[i] * iu;
        prow[kv] = e2[i] * im;
    }
}

// ---------------------------------------------------------------------------
// Host launch
// ---------------------------------------------------------------------------
extern "C" void kernel_launch(void* const* d_in, const int* in_sizes, int n_in,
                              void* d_out, int out_size)
{
    const float* x        = (const float*)d_in[0];
    const float* z        = (const float*)d_in[1];
    const float* key_rope = (const float*)d_in[2];
    const int*   vlens    = (const int*)  d_in[3];
    const float* W_latent = (const float*)d_in[4];
    const float* W_q_down = (const float*)d_in[5];
    const float* b_q_down = (const float*)d_in[6];
    const float* W_q_up   = (const float*)d_in[7];
    const float* W_k_up   = (const float*)d_in[8];
    const float* W_v_up   = (const float*)d_in[9];
    const float* W_x_rope = (const float*)d_in[10];
    const float* W_k_rope = (const float*)d_in[11];
    const float* W_o      = (const float*)d_in[12];
    float* out = (float*)d_out;

    float *p_qlat, *p_qx, *p_query, *p_qrope, *p_kx, *p_keyc, *p_value,
          *p_qfull, *p_kfull, *p_headout, *p_probs;
    cudaGetSymbolAddress((void**)&p_qlat,    g_qlat);
    cudaGetSymbolAddress((void**)&p_qx,      g_qx);
    cudaGetSymbolAddress((void**)&p_query,   g_query);
    cudaGetSymbolAddress((void**)&p_qrope,   g_qrope);
    cudaGetSymbolAddress((void**)&p_kx,      g_kx);
    cudaGetSymbolAddress((void**)&p_keyc,    g_keyc);
    cudaGetSymbolAddress((void**)&p_value,   g_value);
    cudaGetSymbolAddress((void**)&p_qfull,   g_qfull);
    cudaGetSymbolAddress((void**)&p_kfull,   g_kfull);
    cudaGetSymbolAddress((void**)&p_headout, g_headout);
    cudaGetSymbolAddress((void**)&p_probs,   g_probs);

    // 1. z_all[:, :1024, :] = z ;  key_rope_all[:, :1024, :] = key_rope
    copy_concat_kernel<<<8192, 256>>>(z,        out + OUT_ZALL);
    copy_concat_kernel<<<8192, 256>>>(key_rope, out + OUT_KRA);

    // 2. z_all[:, 1024:, :] = x @ W_latent   (batched over B)
    gemm_nn_kernel<<<dim3(16, 8, 2), 256>>>(
        x, W_latent, nullptr, out + OUT_ZALL + 1024L * 1024,
        1024, 1024, 2048, 2048, 1024, 1024,
        1, 1024L * 2048, 0, 0, 0, 2048L * 1024, 0, 1.f);

    // 3. q_lat = x @ W_q_down + b_q_down    (M=2048)
    gemm_nn_kernel<<<dim3(16, 16, 1), 256>>>(
        x, W_q_down, b_q_down, p_qlat,
        2048, 1024, 2048, 2048, 1024, 1024,
        1, 0, 0, 0, 0, 0, 0, 1.f);

    // 4. query = q_lat @ W_q_up ; qx = q_lat @ W_x_rope
    gemm_nn_kernel<<<dim3(16, 16, 1), 256>>>(
        p_qlat, W_q_up, nullptr, p_query,
        2048, 1024, 1024, 1024, 1024, 1024,
        1, 0, 0, 0, 0, 0, 0, 1.f);
    gemm_nn_kernel<<<dim3(16, 16, 1), 256>>>(
        p_qlat, W_x_rope, nullptr, p_qx,
        2048, 1024, 1024, 1024, 1024, 1024,
        1, 0, 0, 0, 0, 0, 0, 1.f);

    // 5. key_c = z_all @ W_k_up ; value = z_all @ W_v_up   (M=4096, z_all read from out)
    gemm_nn_kernel<<<dim3(16, 32, 1), 256>>>(
        out + OUT_ZALL, W_k_up, nullptr, p_keyc,
        4096, 1024, 1024, 1024, 1024, 1024,
        1, 0, 0, 0, 0, 0, 0, 1.f);
    gemm_nn_kernel<<<dim3(16, 32, 1), 256>>>(
        out + OUT_ZALL, W_v_up, nullptr, p_value,
        4096, 1024, 1024, 1024, 1024, 1024,
        1, 0, 0, 0, 0, 0, 0, 1.f);

    // 6. kx = x @ W_k_rope
    gemm_nn_kernel<<<dim3(16, 16, 1), 256>>>(
        x, W_k_rope, nullptr, p_kx,
        2048, 1024, 2048, 2048, 1024, 1024,
        1, 0, 0, 0, 0, 0, 0, 1.f);

    // 7. rotary: q_rope = rope(qx); key_rope_all[:, 1024:, :] = rope(kx)
    rotary_kernel<<<4096, 256>>>(p_qx, p_qrope, 0);
    rotary_kernel<<<4096, 256>>>(p_kx, out + OUT_KRA, 1);

    // 8. pack per-head q/k (reshape of the feature-concat into 16 x 128 chunks)
    pack_q_kernel<<<16384, 256>>>(p_query, p_qrope, p_qfull);
    pack_k_kernel<<<32768, 256>>>(p_keyc, out + OUT_KRA, p_kfull);

    // 9. scores = (1/sqrt(128)) * Q @ K^T   (batch=32 heads)
    gemm_nt_kernel<<<dim3(32, 8, 32), 256>>>(
        p_qfull, p_kfull, out + OUT_SCORES,
        1024, 2048, 128, 128, 128, 2048,
        1024L * 128, 2048L * 128, 1024L * 2048, 0.088388347648318447f);

    // 10. dual softmax -> attn_weights (out) + probs (scratch)
    softmax_kernel<<<32768, 256>>>(out + OUT_SCORES, vlens, out + OUT_ATTN, p_probs);

    // 11. head_out[b,l,h,:] = probs[b,h] @ v[b,:,h*64:(h+1)*64]   (batch=32, HD=16)
    gemm_nn_kernel<<<dim3(1, 8, 32), 256>>>(
        p_probs, p_value, nullptr, p_headout,
        1024, 64, 2048, 2048, 1024, 1024,
        16, 16L * 1024 * 2048, 1024L * 2048,
        2048L * 1024, 64L,
        1024L * 1024, 64L, 1.f);

    // 12. out = head_out @ W_o
    gemm_nn_kernel<<<dim3(32, 16, 1), 256>>>(
        p_headout, W_o, nullptr, out + OUT_OUT,
        2048, 2048, 1024, 1024, 2048, 2048,
        1, 0, 0, 0, 0, 0, 0, 1.f);
}

// round 2
// speedup vs baseline: 1.0780x; 1.0780x over previous
#include <cuda_runtime.h>

// ---------------------------------------------------------------------------
// Problem constants / output layout (floats), tuple order:
// out, z_all, key_rope_all, attn_weights, scores
// ---------------------------------------------------------------------------
#define OUT_OUT    0L
#define OUT_ZALL   4194304L
#define OUT_KRA    8388608L
#define OUT_ATTN   12582912L
#define OUT_SCORES 79691776L

// ---------------------------------------------------------------------------
// Scratch (static device arrays; no cudaMalloc allowed)
// ---------------------------------------------------------------------------
__device__ float g_qlat   [2048 * 1024];
__device__ float g_qx     [2048 * 1024];
__device__ float g_query  [2048 * 1024];
__device__ float g_qrope  [2048 * 1024];
__device__ float g_kx     [2048 * 1024];
__device__ float g_keyc   [2 * 2048 * 1024];
__device__ float g_value  [2 * 2048 * 1024];
__device__ float g_qfull  [2 * 16 * 1024 * 128];
__device__ float g_kfull  [2 * 16 * 2048 * 128];
__device__ float g_headout[2048 * 1024];
__device__ float g_probs  [67108864];

// ---------------------------------------------------------------------------
// f32x2 packed-FMA helpers (sm_103a FFMA2 path)
// ---------------------------------------------------------------------------
union F4U { float4 v; unsigned long long u[2]; };

#define FMA2(c, a, b) \
    asm("fma.rn.f32x2 %0, %1, %2, %0;" : "+l"(c) : "l"(a), "l"(b))

#define DUP2(d, s) \
    asm("mov.b64 %0, {%1, %1};" : "=l"(d) : "f"(s))

// ---------------------------------------------------------------------------
// 128x128 NN SGEMM, f32x2 microkernel, double-buffered smem.
// 256 threads, 8x8 microtile, K-step 8. C = alpha*A@B + bias.
// grid: (N/128, M/128, Z); simple per-Z strides.
// ---------------------------------------------------------------------------
__global__ void __launch_bounds__(256, 2) gemm128_nn(
    const float* __restrict__ A, const float* __restrict__ B,
    const float* __restrict__ bias, float* __restrict__ C,
    int K, int lda, int ldb, int ldc,
    long sA, long sB, long sC, float alpha)
{
    __shared__ float As[2][8][128];
    __shared__ float Bs[2][8][128];

    const float* Ab = A + (long)blockIdx.z * sA + (long)blockIdx.y * 128 * lda;
    const float* Bb = B + (long)blockIdx.z * sB + (long)blockIdx.x * 128;
    float*       Cb = C + (long)blockIdx.z * sC
                       + (long)blockIdx.y * 128 * ldc + (long)blockIdx.x * 128;

    int tid = threadIdx.x;
    int ar  = tid >> 1;              // A load row 0..127
    int akc = (tid & 1) << 2;        // A load k offset 0/4
    int br  = tid >> 5;              // B load row 0..7
    int bc  = (tid & 31) << 2;       // B load col 0..124
    int tm  = (tid >> 4) << 3;       // compute row base
    int tn  = (tid & 15) << 3;       // compute col base

    unsigned long long acc[8][4] = {};   // f32x2 pairs along N

    int nslab = K >> 3;
    {
        float4 pa = *(const float4*)(Ab + (long)ar * lda + akc);
        float4 pb = *(const float4*)(Bb + (long)br * ldb + bc);
        As[0][akc + 0][ar] = pa.x; As[0][akc + 1][ar] = pa.y;
        As[0][akc + 2][ar] = pa.z; As[0][akc + 3][ar] = pa.w;
        *(float4*)(&Bs[0][br][bc]) = pb;
    }
    __syncthreads();

    float4 pa, pb;
    for (int s = 0; s < nslab; s++) {
        int cur = s & 1;
        bool more = (s + 1 < nslab);
        if (more) {
            int kt = (s + 1) << 3;
            pa = *(const float4*)(Ab + (long)ar * lda + kt + akc);
            pb = *(const float4*)(Bb + (long)(kt + br) * ldb + bc);
        }
        #pragma unroll
        for (int k = 0; k < 8; k++) {
            F4U a0, a1, b0, b1;
            a0.v = *(const float4*)(&As[cur][k][tm]);
            a1.v = *(const float4*)(&As[cur][k][tm + 4]);
            b0.v = *(const float4*)(&Bs[cur][k][tn]);
            b1.v = *(const float4*)(&Bs[cur][k][tn + 4]);
            float av[8] = {a0.v.x, a0.v.y, a0.v.z, a0.v.w,
                           a1.v.x, a1.v.y, a1.v.z, a1.v.w};
            #pragma unroll
            for (int i = 0; i < 8; i++) {
                unsigned long long a2;
                DUP2(a2, av[i]);
                FMA2(acc[i][0], a2, b0.u[0]);
                FMA2(acc[i][1], a2, b0.u[1]);
                FMA2(acc[i][2], a2, b1.u[0]);
                FMA2(acc[i][3], a2, b1.u[1]);
            }
        }
        if (more) {
            int nxt = cur ^ 1;
            As[nxt][akc + 0][ar] = pa.x; As[nxt][akc + 1][ar] = pa.y;
            As[nxt][akc + 2][ar] = pa.z; As[nxt][akc + 3][ar] = pa.w;
            *(float4*)(&Bs[nxt][br][bc]) = pb;
        }
        __syncthreads();
    }

    float bv[8] = {0.f, 0.f, 0.f, 0.f, 0.f, 0.f, 0.f, 0.f};
    if (bias) {
        #pragma unroll
        for (int j = 0; j < 8; j++) bv[j] = bias[blockIdx.x * 128 + tn + j];
    }
    #pragma unroll
    for (int i = 0; i < 8; i++) {
        F4U t0, t1;
        t0.u[0] = acc[i][0]; t0.u[1] = acc[i][1];
        t1.u[0] = acc[i][2]; t1.u[1] = acc[i][3];
        float4 o0, o1;
        o0.x = t0.v.x * alpha + bv[0]; o0.y = t0.v.y * alpha + bv[1];
        o0.z = t0.v.z * alpha + bv[2]; o0.w = t0.v.w * alpha + bv[3];
        o1.x = t1.v.x * alpha + bv[4]; o1.y = t1.v.y * alpha + bv[5];
        o1.z = t1.v.z * alpha + bv[6]; o1.w = t1.v.w * alpha + bv[7];
        *(float4*)(Cb + (long)(tm + i) * ldc + tn)     = o0;
        *(float4*)(Cb + (long)(tm + i) * ldc + tn + 4) = o1;
    }
}

// ---------------------------------------------------------------------------
// 128x128 NT SGEMM (scores): C = alpha * A @ B^T, B is (N x K) row-major.
// ---------------------------------------------------------------------------
__global__ void __launch_bounds__(256, 2) gemm128_nt(
    const float* __restrict__ A, const float* __restrict__ B,
    float* __restrict__ C,
    int K, int lda, int ldb, int ldc,
    long sA, long sB, long sC, float alpha)
{
    __shared__ float As[2][8][128];
    __shared__ float Bs[2][8][128];

    const float* Ab = A + (long)blockIdx.z * sA + (long)blockIdx.y * 128 * lda;
    const float* Bb = B + (long)blockIdx.z * sB + (long)blockIdx.x * 128 * ldb;
    float*       Cb = C + (long)blockIdx.z * sC
                       + (long)blockIdx.y * 128 * ldc + (long)blockIdx.x * 128;

    int tid = threadIdx.x;
    int ar  = tid >> 1;
    int akc = (tid & 1) << 2;
    int tm  = (tid >> 4) << 3;
    int tn  = (tid & 15) << 3;

    unsigned long long acc[8][4] = {};

    int nslab = K >> 3;
    {
        float4 pa = *(const float4*)(Ab + (long)ar * lda + akc);
        float4 pb = *(const float4*)(Bb + (long)ar * ldb + akc);
        As[0][akc + 0][ar] = pa.x; As[0][akc + 1][ar] = pa.y;
        As[0][akc + 2][ar] = pa.z; As[0][akc + 3][ar] = pa.w;
        Bs[0][akc + 0][ar] = pb.x; Bs[0][akc + 1][ar] = pb.y;
        Bs[0][akc + 2][ar] = pb.z; Bs[0][akc + 3][ar] = pb.w;
    }
    __syncthreads();

    float4 pa, pb;
    for (int s = 0; s < nslab; s++) {
        int cur = s & 1;
        bool more = (s + 1 < nslab);
        if (more) {
            int kt = (s + 1) << 3;
            pa = *(const float4*)(Ab + (long)ar * lda + kt + akc);
            pb = *(const float4*)(Bb + (long)ar * ldb + kt + akc);
        }
        #pragma unroll
        for (int k = 0; k < 8; k++) {
            F4U a0, a1, b0, b1;
            a0.v = *(const float4*)(&As[cur][k][tm]);
            a1.v = *(const float4*)(&As[cur][k][tm + 4]);
            b0.v = *(const float4*)(&Bs[cur][k][tn]);
            b1.v = *(const float4*)(&Bs[cur][k][tn + 4]);
            float av[8] = {a0.v.x, a0.v.y, a0.v.z, a0.v.w,
                           a1.v.x, a1.v.y, a1.v.z, a1.v.w};
            #pragma unroll
            for (int i = 0; i < 8; i++) {
                unsigned long long a2;
                DUP2(a2, av[i]);
                FMA2(acc[i][0], a2, b0.u[0]);
                FMA2(acc[i][1], a2, b0.u[1]);
                FMA2(acc[i][2], a2, b1.u[0]);
                FMA2(acc[i][3], a2, b1.u[1]);
            }
        }
        if (more) {
            int nxt = cur ^ 1;
            As[nxt][akc + 0][ar] = pa.x; As[nxt][akc + 1][ar] = pa.y;
            As[nxt][akc + 2][ar] = pa.z; As[nxt][akc + 3][ar] = pa.w;
            Bs[nxt][akc + 0][ar] = pb.x; Bs[nxt][akc + 1][ar] = pb.y;
            Bs[nxt][akc + 2][ar] = pb.z; Bs[nxt][akc + 3][ar] = pb.w;
        }
        __syncthreads();
    }

    #pragma unroll
    for (int i = 0; i < 8; i++) {
        F4U t0, t1;
        t0.u[0] = acc[i][0]; t0.u[1] = acc[i][1];
        t1.u[0] = acc[i][2]; t1.u[1] = acc[i][3];
        float4 o0, o1;
        o0.x = t0.v.x * alpha; o0.y = t0.v.y * alpha;
        o0.z = t0.v.z * alpha; o0.w = t0.v.w * alpha;
        o1.x = t1.v.x * alpha; o1.y = t1.v.y * alpha;
        o1.z = t1.v.z * alpha; o1.w = t1.v.w * alpha;
        *(float4*)(Cb + (long)(tm + i) * ldc + tn)     = o0;
        *(float4*)(Cb + (long)(tm + i) * ldc + tn + 4) = o1;
    }
}

// ---------------------------------------------------------------------------
// 128x64 NN (probs @ value per head). 128 threads, 8x8 microtile,
// double-buffered, f32x2. grid: (1, M/128, Z) with z1=z/HD, z2=z%HD strides.
// ---------------------------------------------------------------------------
__global__ void __launch_bounds__(128, 4) gemm_av(
    const float* __restrict__ A, const float* __restrict__ B,
    float* __restrict__ C,
    int K, int lda, int ldb, int ldc,
    int HD, long sA1, long sA2, long sB1, long sB2, long sC1, long sC2)
{
    __shared__ float As[2][8][128];
    __shared__ float Bs[2][8][64];

    int z  = blockIdx.z;
    int z1 = z / HD, z2 = z % HD;
    const float* Ab = A + (long)z1 * sA1 + (long)z2 * sA2 + (long)blockIdx.y * 128 * lda;
    const float* Bb = B + (long)z1 * sB1 + (long)z2 * sB2;
    float*       Cb = C + (long)z1 * sC1 + (long)z2 * sC2 + (long)blockIdx.y * 128 * ldc;

    int tid = threadIdx.x;
    int ar  = tid >> 1;              // 0..63 (plus ar+64)
    int akc = (tid & 1) << 2;
    int br  = tid >> 4;              // 0..7
    int bc  = (tid & 15) << 2;       // 0..60
    int tm  = (tid >> 3) << 3;       // 0..120
    int tn  = (tid & 7) << 3;        // 0..56

    unsigned long long acc[8][4] = {};

    int nslab = K >> 3;
    {
        float4 pa0 = *(const float4*)(Ab + (long)ar * lda + akc);
        float4 pa1 = *(const float4*)(Ab + (long)(ar + 64) * lda + akc);
        float4 pb  = *(const float4*)(Bb + (long)br * ldb + bc);
        As[0][akc + 0][ar] = pa0.x; As[0][akc + 1][ar] = pa0.y;
        As[0][akc + 2][ar] = pa0.z; As[0][akc + 3][ar] = pa0.w;
        As[0][akc + 0][ar + 64] = pa1.x; As[0][akc + 1][ar + 64] = pa1.y;
        As[0][akc + 2][ar + 64] = pa1.z; As[0][akc + 3][ar + 64] = pa1.w;
        *(float4*)(&Bs[0][br][bc]) = pb;
    }
    __syncthreads();

    float4 pa0, pa1, pb;
    for (int s = 0; s < nslab; s++) {
        int cur = s & 1;
        bool more = (s + 1 < nslab);
        if (more) {
            int kt = (s + 1) << 3;
            pa0 = *(const float4*)(Ab + (long)ar * lda + kt + akc);
            pa1 = *(const float4*)(Ab + (long)(ar + 64) * lda + kt + akc);
            pb  = *(const float4*)(Bb + (long)(kt + br) * ldb + bc);
        }
        #pragma unroll
        for (int k = 0; k < 8; k++) {
            F4U a0, a1, b0, b1;
            a0.v = *(const float4*)(&As[cur][k][tm]);
            a1.v = *(const float4*)(&As[cur][k][tm + 4]);
            b0.v = *(const float4*)(&Bs[cur][k][tn]);
            b1.v = *(const float4*)(&Bs[cur][k][tn + 4]);
            float av[8] = {a0.v.x, a0.v.y, a0.v.z, a0.v.w,
                           a1.v.x, a1.v.y, a1.v.z, a1.v.w};
            #pragma unroll
            for (int i = 0; i < 8; i++) {
                unsigned long long a2;
                DUP2(a2, av[i]);
                FMA2(acc[i][0], a2, b0.u[0]);
                FMA2(acc[i][1], a2, b0.u[1]);
                FMA2(acc[i][2], a2, b1.u[0]);
                FMA2(acc[i][3], a2, b1.u[1]);
            }
        }
        if (more) {
            int nxt = cur ^ 1;
            As[nxt][akc + 0][ar] = pa0.x; As[nxt][akc + 1][ar] = pa0.y;
            As[nxt][akc + 2][ar] = pa0.z; As[nxt][akc + 3][ar] = pa0.w;
            As[nxt][akc + 0][ar + 64] = pa1.x; As[nxt][akc + 1][ar + 64] = pa1.y;
            As[nxt][akc + 2][ar + 64] = pa1.z; As[nxt][akc + 3][ar + 64] = pa1.w;
            *(float4*)(&Bs[nxt][br][bc]) = pb;
        }
        __syncthreads();
    }

    #pragma unroll
    for (int i = 0; i < 8; i++) {
        F4U t0, t1;
        t0.u[0] = acc[i][0]; t0.u[1] = acc[i][1];
        t1.u[0] = acc[i][2]; t1.u[1] = acc[i][3];
        *(float4*)(Cb + (long)(tm + i) * ldc + tn)     = t0.v;
        *(float4*)(Cb + (long)(tm + i) * ldc + tn + 4) = t1.v;
    }
}

// ---------------------------------------------------------------------------
// Elementwise helpers (unchanged from round 1)
// ---------------------------------------------------------------------------
__global__ void copy_concat_kernel(const float* __restrict__ src, float* __restrict__ dst)
{
    long i = (long)blockIdx.x * 256 + threadIdx.x;
    if (i >= 2L * 1024 * 1024) return;
    long r = i >> 10, c = i & 1023;
    long b = r >> 10, l = r & 1023;
    dst[((b * 2048) + l) * 1024 + c] = src[i];
}

__global__ void rotary_kernel(const float* __restrict__ src, float* __restrict__ dst, int mode)
{
    int idx = blockIdx.x * 256 + threadIdx.x;
    if (idx >= 2048 * 16 * 32) return;
    int i = idx & 31;
    int h = (idx >> 5) & 15;
    int r = idx >> 9;
    int pos = r & 1023;
    float fr = expf(-9.2103403719761836f * (float)i / 32.0f);
    float ang = (float)pos * fr;
    float sn, cs;
    sincosf(ang, &sn, &cs);
    const float* s = src + (long)r * 1024 + h * 64 + i;
    float s1 = s[0], s2 = s[32];
    long drow = mode ? ((long)(r >> 10) * 2048 + 1024 + (r & 1023)) : (long)r;
    float* d = dst + drow * 1024 + h * 64 + i;
    d[0]  = s1 * cs - s2 * sn;
    d[32] = s1 * sn + s2 * cs;
}

__global__ void pack_q_kernel(const float* __restrict__ q, const float* __restrict__ qr,
                              float* __restrict__ qf)
{
    long idx = (long)blockIdx.x * 256 + threadIdx.x;
    if (idx >= 4194304L) return;
    long d = idx & 127;
    long l = (idx >> 7) & 1023;
    long h = (idx >> 17) & 15;
    long b = idx >> 21;
    long c = h * 128 + d;
    const float* src = (c < 1024) ? q : qr;
    qf[idx] = src[(b * 1024 + l) * 1024 + (c & 1023)];
}

__global__ void pack_k_kernel(const float* __restrict__ kc, const float* __restrict__ kra,
                              float* __restrict__ kf)
{
    long idx = (long)blockIdx.x * 256 + threadIdx.x;
    if (idx >= 8388608L) return;
    long d  = idx & 127;
    long kv = (idx >> 7) & 2047;
    long h  = (idx >> 18) & 15;
    long b  = idx >> 22;
    long c = h * 128 + d;
    const float* src = (c < 1024) ? kc : kra;
    kf[idx] = src[(b * 2048 + kv) * 1024 + (c & 1023)];
}

__global__ void __launch_bounds__(256) softmax_kernel(
    const float* __restrict__ scores, const int* __restrict__ vlens,
    float* __restrict__ attn, float* __restrict__ probs)
{
    int row = blockIdx.x;
    int l = row & 1023;
    int b = row >> 14;
    int vl = vlens[b * 1024 + l];
    const float* s = scores + (long)row * 2048;
    int tid = threadIdx.x;

    float v[8], e2[8];
    float mu = -1e30f, mm = -1e30f;
    #pragma unroll
    for (int i = 0; i < 8; i++) {
        int kv = tid + (i << 8);
        v[i] = s[kv];
        mu = fmaxf(mu, v[i]);
        if (kv < vl) mm = fmaxf(mm, v[i]);
    }
    __shared__ float red[16];
    #pragma unroll
    for (int o = 16; o > 0; o >>= 1) {
        mu = fmaxf(mu, __shfl_xor_sync(0xffffffffu, mu, o));
        mm = fmaxf(mm, __shfl_xor_sync(0xffffffffu, mm, o));
    }
    int w = tid >> 5, lane = tid & 31;
    if (lane == 0) { red[w] = mu; red[w + 8] = mm; }
    __syncthreads();
    mu = -1e30f; mm = -1e30f;
    #pragma unroll
    for (int i = 0; i < 8; i++) { mu = fmaxf(mu, red[i]); mm = fmaxf(mm, red[8 + i]); }
    __syncthreads();

    float su = 0.f, sm = 0.f;
    #pragma unroll
    for (int i = 0; i < 8; i++) {
        int kv = tid + (i << 8);
        float eu = expf(v[i] - mu);
        float em = (kv < vl) ? expf(v[i] - mm) : 0.f;
        v[i] = eu; e2[i] = em;
        su += eu; sm += em;
    }
    #pragma unroll
    for (int o = 16; o > 0; o >>= 1) {
        su += __shfl_xor_sync(0xffffffffu, su, o);
        sm += __shfl_xor_sync(0xffffffffu, sm, o);
    }
    if (lane == 0) { red[w] = su; red[w + 8] = sm; }
    __syncthreads();
    su = 0.f; sm = 0.f;
    #pragma unroll
    for (int i = 0; i < 8; i++) { su += red[i]; sm += red[8 + i]; }
    float iu = 1.f / su, im = 1.f / sm;

    float* arow = attn  + (long)row * 2048;
    float* prow = probs + (long)row * 2048;
    #pragma unroll
    for (int i = 0; i < 8; i++) {
        int kv = tid + (i << 8);
        arow[kv] = v[i] * iu;
        prow[kv] = e2[i] * im;
    }
}

// ---------------------------------------------------------------------------
// Host launch
// ---------------------------------------------------------------------------
extern "C" void kernel_launch(void* const* d_in, const int* in_sizes, int n_in,
                              void* d_out, int out_size)
{
    const float* x        = (const float*)d_in[0];
    const float* z        = (const float*)d_in[1];
    const float* key_rope = (const float*)d_in[2];
    const int*   vlens    = (const int*)  d_in[3];
    const float* W_latent = (const float*)d_in[4];
    const float* W_q_down = (const float*)d_in[5];
    const float* b_q_down = (const float*)d_in[6];
    const float* W_q_up   = (const float*)d_in[7];
    const float* W_k_up   = (const float*)d_in[8];
    const float* W_v_up   = (const float*)d_in[9];
    const float* W_x_rope = (const float*)d_in[10];
    const float* W_k_rope = (const float*)d_in[11];
    const float* W_o      = (const float*)d_in[12];
    float* out = (float*)d_out;

    float *p_qlat, *p_qx, *p_query, *p_qrope, *p_kx, *p_keyc, *p_value,
          *p_qfull, *p_kfull, *p_headout, *p_probs;
    cudaGetSymbolAddress((void**)&p_qlat,    g_qlat);
    cudaGetSymbolAddress((void**)&p_qx,      g_qx);
    cudaGetSymbolAddress((void**)&p_query,   g_query);
    cudaGetSymbolAddress((void**)&p_qrope,   g_qrope);
    cudaGetSymbolAddress((void**)&p_kx,      g_kx);
    cudaGetSymbolAddress((void**)&p_keyc,    g_keyc);
    cudaGetSymbolAddress((void**)&p_value,   g_value);
    cudaGetSymbolAddress((void**)&p_qfull,   g_qfull);
    cudaGetSymbolAddress((void**)&p_kfull,   g_kfull);
    cudaGetSymbolAddress((void**)&p_headout, g_headout);
    cudaGetSymbolAddress((void**)&p_probs,   g_probs);

    // 1. z_all[:, :1024, :] = z ;  key_rope_all[:, :1024, :] = key_rope
    copy_concat_kernel<<<8192, 256>>>(z,        out + OUT_ZALL);
    copy_concat_kernel<<<8192, 256>>>(key_rope, out + OUT_KRA);

    // 2. z_all[:, 1024:, :] = x @ W_latent  (batched over B)
    gemm128_nn<<<dim3(8, 8, 2), 256>>>(
        x, W_latent, nullptr, out + OUT_ZALL + 1024L * 1024,
        2048, 2048, 1024, 1024,
        1024L * 2048, 0, 2048L * 1024, 1.f);

    // 3. q_lat = x @ W_q_down + b_q_down
    gemm128_nn<<<dim3(8, 16, 1), 256>>>(
        x, W_q_down, b_q_down, p_qlat,
        2048, 2048, 1024, 1024, 0, 0, 0, 1.f);

    // 4. query = q_lat @ W_q_up ; qx = q_lat @ W_x_rope
    gemm128_nn<<<dim3(8, 16, 1), 256>>>(
        p_qlat, W_q_up, nullptr, p_query,
        1024, 1024, 1024, 1024, 0, 0, 0, 1.f);
    gemm128_nn<<<dim3(8, 16, 1), 256>>>(
        p_qlat, W_x_rope, nullptr, p_qx,
        1024, 1024, 1024, 1024, 0, 0, 0, 1.f);

    // 5. key_c = z_all @ W_k_up ; value = z_all @ W_v_up  (M=4096)
    gemm128_nn<<<dim3(8, 32, 1), 256>>>(
        out + OUT_ZALL, W_k_up, nullptr, p_keyc,
        1024, 1024, 1024, 1024, 0, 0, 0, 1.f);
    gemm128_nn<<<dim3(8, 32, 1), 256>>>(
        out + OUT_ZALL, W_v_up, nullptr, p_value,
        1024, 1024, 1024, 1024, 0, 0, 0, 1.f);

    // 6. kx = x @ W_k_rope
    gemm128_nn<<<dim3(8, 16, 1), 256>>>(
        x, W_k_rope, nullptr, p_kx,
        2048, 2048, 1024, 1024, 0, 0, 0, 1.f);

    // 7. rotary
    rotary_kernel<<<4096, 256>>>(p_qx, p_qrope, 0);
    rotary_kernel<<<4096, 256>>>(p_kx, out + OUT_KRA, 1);

    // 8. pack per-head q/k
    pack_q_kernel<<<16384, 256>>>(p_query, p_qrope, p_qfull);
    pack_k_kernel<<<32768, 256>>>(p_keyc, out + OUT_KRA, p_kfull);

    // 9. scores = (1/sqrt(128)) * Q @ K^T   (batch = 32 (b,h))
    gemm128_nt<<<dim3(16, 8, 32), 256>>>(
        p_qfull, p_kfull, out + OUT_SCORES,
        128, 128, 128, 2048,
        1024L * 128, 2048L * 128, 1024L * 2048, 0.088388347648318447f);

    // 10. dual softmax
    softmax_kernel<<<32768, 256>>>(out + OUT_SCORES, vlens, out + OUT_ATTN, p_probs);

    // 11. head_out = probs @ value (per head slice)
    gemm_av<<<dim3(1, 8, 32), 128>>>(
        p_probs, p_value, p_headout,
        2048, 2048, 1024, 1024,
        16, 16L * 1024 * 2048, 1024L * 2048,
        2048L * 1024, 64L,
        1024L * 1024, 64L);

    // 12. out = head_out @ W_o
    gemm128_nn<<<dim3(16, 16, 1), 256>>>(
        p_headout, W_o, nullptr, out + OUT_OUT,
        1024, 1024, 2048, 2048, 0, 0, 0, 1.f);
}

// round 4
// speedup vs baseline: 2.0746x; 1.9246x over previous
#include <cuda_runtime.h>
#include <cuda_bf16.h>
#include <cstdint>

typedef __nv_bfloat16 bf16;

// Output layout (floats): out, z_all, key_rope_all, attn_weights, scores
#define OUT_OUT    0L
#define OUT_ZALL   4194304L
#define OUT_KRA    8388608L
#define OUT_ATTN   12582912L
#define OUT_SCORES 79691776L

// ---------------------------------------------------------------------------
// Scratch
// ---------------------------------------------------------------------------
__device__ float g_query [2048L*1024];
__device__ float g_qx    [2048L*1024];
__device__ float g_qrope [2048L*1024];
__device__ float g_kx    [2048L*1024];
__device__ float g_keyc  [4096L*1024];
__device__ float g_value [4096L*1024];

__device__ bf16 g_xh[2048L*2048], g_xl[2048L*2048];
__device__ bf16 g_zallh[4096L*1024], g_zalll[4096L*1024];
__device__ bf16 g_qlath[2048L*1024], g_qlatl[2048L*1024];
__device__ bf16 g_qfh[4194304L], g_qfl[4194304L];
__device__ bf16 g_kfh[8388608L], g_kfl[8388608L];
__device__ bf16 g_vth[2L*1024*2048], g_vtl[2L*1024*2048];
__device__ bf16 g_hoh[2048L*1024], g_hol[2048L*1024];
__device__ bf16 g_pbh[67108864L], g_pbl[67108864L];

__device__ bf16 g_WlatTh[2097152], g_WlatTl[2097152];
__device__ bf16 g_WqdTh [2097152], g_WqdTl [2097152];
__device__ bf16 g_WquTh [1048576], g_WquTl [1048576];
__device__ bf16 g_WxrTh [1048576], g_WxrTl [1048576];
__device__ bf16 g_WkuTh [1048576], g_WkuTl [1048576];
__device__ bf16 g_WvuTh [1048576], g_WvuTl [1048576];
__device__ bf16 g_WkrTh [2097152], g_WkrTl [2097152];
__device__ bf16 g_WoTh  [2097152], g_WoTl  [2097152];

// ---------------------------------------------------------------------------
// Helpers (baseline PTX only — no *_a arch features)
// ---------------------------------------------------------------------------
__device__ __forceinline__ uint32_t smem_u32(const void* p) {
    uint32_t a;
    asm("{ .reg .u64 t; cvta.to.shared.u64 t, %1; cvt.u32.u64 %0, t; }" : "=r"(a) : "l"(p));
    return a;
}
#define SW128X(o) ((o) ^ (((o) >> 3) & 0x70))

__device__ __forceinline__ void ldm4(uint32_t* r, uint32_t addr) {
    asm volatile("ldmatrix.sync.aligned.m8n8.x4.shared.b16 {%0,%1,%2,%3}, [%4];"
        : "=r"(r[0]), "=r"(r[1]), "=r"(r[2]), "=r"(r[3]) : "r"(addr));
}
__device__ __forceinline__ void mma_bf16(float* c, const uint32_t* a, const uint32_t* b) {
    asm volatile("mma.sync.aligned.m16n8k16.row.col.f32.bf16.bf16.f32 "
        "{%0,%1,%2,%3}, {%4,%5,%6,%7}, {%8,%9}, {%0,%1,%2,%3};"
        : "+f"(c[0]), "+f"(c[1]), "+f"(c[2]), "+f"(c[3])
        : "r"(a[0]), "r"(a[1]), "r"(a[2]), "r"(a[3]), "r"(b[0]), "r"(b[1]));
}

// ---------------------------------------------------------------------------
// Split-bf16 HMMA GEMM:
//   C(MxN,f32) = alpha * (Ah+Al)(MxK) @ (Bh+Bl)(NxK)^T + bias   (Al@Bl dropped)
// A,B bf16 K-major. Optional split outputs Ch/Cl. CTA tile 128 x NT, K-chunk 64.
// grid: (N/NT, M/128, Z); z1=z/HD, z2=z%HD per-operand strides.
// ---------------------------------------------------------------------------
template<int NT>
__global__ void __launch_bounds__(256) gemm_tc(
    const bf16* __restrict__ Ah, const bf16* __restrict__ Al,
    const bf16* __restrict__ Bh, const bf16* __restrict__ Bl,
    float* C, const float* bias, bf16* Ch, bf16* Cl,
    int K, int lda, int ldb, int ldc,
    int HD, long sA1, long sA2, long sB1, long sB2, long sC1, long sC2,
    float alpha)
{
    constexpr int MI  = (NT == 128) ? 4 : 2;   // m16 tiles per warp
    constexpr int NB  = NT / 32;               // B 16B-chunks per thread per buffer
    constexpr int ABY = 128 * 128;             // 16 KB
    constexpr int BBY = NT * 128;

    extern __shared__ char smem[];
    uint32_t base = (smem_u32(smem) + 1023u) & ~1023u;
    uint32_t aT[2] = {base, base + ABY};
    uint32_t bT[2] = {base + 2u*ABY, base + 2u*ABY + (uint32_t)BBY};

    int tid = threadIdx.x;
    int lane = tid & 31, wid = tid >> 5;

    int wm = (NT == 128) ? (wid & 1) * 64 : (wid & 3) * 32;
    int wn = (NT == 128) ? (wid >> 1) * 32 : (wid >> 2) * 32;

    int z = blockIdx.z;
    int z1 = z / HD, z2 = z - z1 * HD;
    long aoff = (long)z1*sA1 + (long)z2*sA2 + (long)blockIdx.y*128*lda;
    long boff = (long)z1*sB1 + (long)z2*sB2 + (long)blockIdx.x*NT*ldb;
    const bf16 *Abh = Ah + aoff, *Abl = Al + aoff;
    const bf16 *Bbh = Bh + boff, *Bbl = Bl + boff;

    // ldmatrix lane->row/chunk mapping
    int a_r = (lane & 7) + (((lane >> 3) & 1) << 3);
    int a_c = (lane >> 4) & 1;
    int b_r = (lane & 7) + ((lane & 16) ? 8 : 0);
    int b_c = (lane >> 3) & 1;

    float acc[MI][4][4];
    #pragma unroll
    for (int i = 0; i < MI; i++)
        #pragma unroll
        for (int j = 0; j < 4; j++)
            #pragma unroll
            for (int q = 0; q < 4; q++) acc[i][j][q] = 0.f;

    int kc = K >> 6;
    int nch = 3 * kc;

    int lr = tid >> 3, lc = tid & 7;            // loader row / 16B-chunk

    // initial chunk -> buffer 0
    {
        #pragma unroll
        for (int it = 0; it < 4; it++) {
            int r = lr + it * 32;
            uint4 v = *(const uint4*)(Abh + (long)r * lda + lc * 8);
            asm volatile("st.shared.v4.b32 [%0], {%1,%2,%3,%4};"
                :: "r"(aT[0] + SW128X(r*128 + lc*16)), "r"(v.x), "r"(v.y), "r"(v.z), "r"(v.w));
        }
        #pragma unroll
        for (int it = 0; it < NB; it++) {
            int r = lr + it * 32;
            uint4 v = *(const uint4*)(Bbh + (long)r * ldb + lc * 8);
            asm volatile("st.shared.v4.b32 [%0], {%1,%2,%3,%4};"
                :: "r"(bT[0] + SW128X(r*128 + lc*16)), "r"(v.x), "r"(v.y), "r"(v.z), "r"(v.w));
        }
    }
    __syncthreads();

    uint4 pa[4], pb[NB];
    for (int c = 0; c < nch; c++) {
        int cur = c & 1;
        bool more = (c + 1 < nch);
        if (more) {
            int cn = c + 1;
            int pass = cn / kc;
            int kk = (cn - pass * kc) << 6;
            const bf16* Ap = (pass == 1) ? Abl : Abh;
            const bf16* Bp = (pass == 2) ? Bbl : Bbh;
            #pragma unroll
            for (int it = 0; it < 4; it++)
                pa[it] = *(const uint4*)(Ap + (long)(lr + it*32) * lda + kk + lc * 8);
            #pragma unroll
            for (int it = 0; it < NB; it++)
                pb[it] = *(const uint4*)(Bp + (long)(lr + it*32) * ldb + kk + lc * 8);
        }

        uint32_t at = aT[cur], bt = bT[cur];
        #pragma unroll
        for (int ks = 0; ks < 4; ks++) {
            uint32_t af[MI][4], bfr[8];
            #pragma unroll
            for (int mi = 0; mi < MI; mi++) {
                int row = wm + mi*16 + a_r;
                ldm4(af[mi], at + row*128 + ((((ks<<1) + a_c) ^ (row & 7)) << 4));
            }
            #pragma unroll
            for (int np = 0; np < 2; np++) {
                int row = wn + np*16 + b_r;
                ldm4(&bfr[np*4], bt + row*128 + ((((ks<<1) + b_c) ^ (row & 7)) << 4));
            }
            #pragma unroll
            for (int mi = 0; mi < MI; mi++)
                #pragma unroll
                for (int ni = 0; ni < 4; ni++)
                    mma_bf16(acc[mi][ni], af[mi], &bfr[ni*2]);
        }

        if (more) {
            int nxt = cur ^ 1;
            #pragma unroll
            for (int it = 0; it < 4; it++) {
                int r = lr + it * 32;
                asm volatile("st.shared.v4.b32 [%0], {%1,%2,%3,%4};"
                    :: "r"(aT[nxt] + SW128X(r*128 + lc*16)),
                       "r"(pa[it].x), "r"(pa[it].y), "r"(pa[it].z), "r"(pa[it].w));
            }
            #pragma unroll
            for (int it = 0; it < NB; it++) {
                int r = lr + it * 32;
                asm volatile("st.shared.v4.b32 [%0], {%1,%2,%3,%4};"
                    :: "r"(bT[nxt] + SW128X(r*128 + lc*16)),
                       "r"(pb[it].x), "r"(pb[it].y), "r"(pb[it].z), "r"(pb[it].w));
            }
        }
        __syncthreads();
    }

    // epilogue
    long coff = (long)z1*sC1 + (long)z2*sC2
              + (long)blockIdx.y*128*ldc + (long)blockIdx.x*NT;
    int colg0 = blockIdx.x * NT;
    #pragma unroll
    for (int mi = 0; mi < MI; mi++) {
        #pragma unroll
        for (int ni = 0; ni < 4; ni++) {
            int col = wn + ni*8 + (lane & 3)*2;
            float bv0 = 0.f, bv1 = 0.f;
            if (bias) { bv0 = bias[colg0 + col]; bv1 = bias[colg0 + col + 1]; }
            int r0 = wm + mi*16 + (lane >> 2);
            float v00 = acc[mi][ni][0]*alpha + bv0, v01 = acc[mi][ni][1]*alpha + bv1;
            float v10 = acc[mi][ni][2]*alpha + bv0, v11 = acc[mi][ni][3]*alpha + bv1;
            if (C) {
                *(float2*)(C + coff + (long)r0*ldc + col)       = make_float2(v00, v01);
                *(float2*)(C + coff + (long)(r0+8)*ldc + col)   = make_float2(v10, v11);
            }
            if (Ch) {
                bf16 h00 = __float2bfloat16(v00), h01 = __float2bfloat16(v01);
                bf16 h10 = __float2bfloat16(v10), h11 = __float2bfloat16(v11);
                *(__nv_bfloat162*)(Ch + coff + (long)r0*ldc + col) = __nv_bfloat162(h00, h01);
                *(__nv_bfloat162*)(Ch + coff + (long)(r0+8)*ldc + col) = __nv_bfloat162(h10, h11);
                bf16 l00 = __float2bfloat16(v00 - __bfloat162float(h00));
                bf16 l01 = __float2bfloat16(v01 - __bfloat162float(h01));
                bf16 l10 = __float2bfloat16(v10 - __bfloat162float(h10));
                bf16 l11 = __float2bfloat16(v11 - __bfloat162float(h11));
                *(__nv_bfloat162*)(Cl + coff + (long)r0*ldc + col) = __nv_bfloat162(l00, l01);
                *(__nv_bfloat162*)(Cl + coff + (long)(r0+8)*ldc + col) = __nv_bfloat162(l10, l11);
            }
        }
    }
}

// ---------------------------------------------------------------------------
// Split f32 -> (bf16 hi, bf16 lo)
// ---------------------------------------------------------------------------
__global__ void split_kernel(const float* __restrict__ in, bf16* __restrict__ oh,
                             bf16* __restrict__ ol, long n)
{
    long i = ((long)blockIdx.x * 256 + threadIdx.x) * 4;
    if (i >= n) return;
    float4 v = *(const float4*)(in + i);
    float a[4] = {v.x, v.y, v.z, v.w};
    bf16 h[4], l[4];
    #pragma unroll
    for (int k = 0; k < 4; k++) {
        h[k] = __float2bfloat16(a[k]);
        l[k] = __float2bfloat16(a[k] - __bfloat162float(h[k]));
    }
    *(__nv_bfloat162*)(oh + i)     = __nv_bfloat162(h[0], h[1]);
    *(__nv_bfloat162*)(oh + i + 2) = __nv_bfloat162(h[2], h[3]);
    *(__nv_bfloat162*)(ol + i)     = __nv_bfloat162(l[0], l[1]);
    *(__nv_bfloat162*)(ol + i + 2) = __nv_bfloat162(l[2], l[3]);
}

// Transpose-split: in (R x C) f32 -> out (C x R) bf16 hi/lo. grid(C/32, R/32, batch)
__global__ void transpose_split(const float* __restrict__ in, bf16* __restrict__ oh,
                                bf16* __restrict__ ol, int R, int C, long sIn, long sOut)
{
    __shared__ float t[32][33];
    long ib = (long)blockIdx.z * sIn, ob = (long)blockIdx.z * sOut;
    int x = blockIdx.x * 32 + threadIdx.x;
    int y0 = blockIdx.y * 32;
    #pragma unroll
    for (int j = threadIdx.y; j < 32; j += 8)
        t[j][threadIdx.x] = in[ib + (long)(y0 + j) * C + x];
    __syncthreads();
    int ox = blockIdx.y * 32 + threadIdx.x;
    int oy0 = blockIdx.x * 32;
    #pragma unroll
    for (int j = threadIdx.y; j < 32; j += 8) {
        float v = t[threadIdx.x][j];
        bf16 h = __float2bfloat16(v);
        long o = ob + (long)(oy0 + j) * R + ox;
        oh[o] = h;
        ol[o] = __float2bfloat16(v - __bfloat162float(h));
    }
}

// ---------------------------------------------------------------------------
// Elementwise helpers
// ---------------------------------------------------------------------------
__global__ void copy_concat_kernel(const float* __restrict__ src, float* __restrict__ dst)
{
    long i = (long)blockIdx.x * 256 + threadIdx.x;
    if (i >= 2L * 1024 * 1024) return;
    long r = i >> 10, c = i & 1023;
    long b = r >> 10, l = r & 1023;
    dst[((b * 2048) + l) * 1024 + c] = src[i];
}

__global__ void rotary_kernel(const float* __restrict__ src, float* __restrict__ dst, int mode)
{
    int idx = blockIdx.x * 256 + threadIdx.x;
    if (idx >= 2048 * 16 * 32) return;
    int i = idx & 31;
    int h = (idx >> 5) & 15;
    int r = idx >> 9;
    int pos = r & 1023;
    float fr = expf(-9.2103403719761836f * (float)i / 32.0f);
    float ang = (float)pos * fr;
    float sn, cs;
    sincosf(ang, &sn, &cs);
    const float* s = src + (long)r * 1024 + h * 64 + i;
    float s1 = s[0], s2 = s[32];
    long drow = mode ? ((long)(r >> 10) * 2048 + 1024 + (r & 1023)) : (long)r;
    float* d = dst + drow * 1024 + h * 64 + i;
    d[0]  = s1 * cs - s2 * sn;
    d[32] = s1 * sn + s2 * cs;
}

__global__ void pack_q_split(const float* __restrict__ q, const float* __restrict__ qr,
                             bf16* __restrict__ qh, bf16* __restrict__ ql)
{
    long idx = (long)blockIdx.x * 256 + threadIdx.x;
    if (idx >= 4194304L) return;
    long d = idx & 127, l = (idx >> 7) & 1023, h = (idx >> 17) & 15, b = idx >> 21;
    long c = h * 128 + d;
    const float* src = (c < 1024) ? q : qr;
    float v = src[(b * 1024 + l) * 1024 + (c & 1023)];
    bf16 hh = __float2bfloat16(v);
    qh[idx] = hh;
    ql[idx] = __float2bfloat16(v - __bfloat162float(hh));
}

__global__ void pack_k_split(const float* __restrict__ kc, const float* __restrict__ kra,
                             bf16* __restrict__ kh, bf16* __restrict__ kl)
{
    long idx = (long)blockIdx.x * 256 + threadIdx.x;
    if (idx >= 8388608L) return;
    long d = idx & 127, kv = (idx >> 7) & 2047, h = (idx >> 18) & 15, b = idx >> 22;
    long c = h * 128 + d;
    const float* src = (c < 1024) ? kc : kra;
    float v = src[(b * 2048 + kv) * 1024 + (c & 1023)];
    bf16 hh = __float2bfloat16(v);
    kh[idx] = hh;
    kl[idx] = __float2bfloat16(v - __bfloat162float(hh));
}

// Dual softmax; probs emitted as split bf16.
__global__ void __launch_bounds__(256) softmax_kernel(
    const float* __restrict__ scores, const int* __restrict__ vlens,
    float* __restrict__ attn, bf16* __restrict__ ph_out, bf16* __restrict__ pl_out)
{
    int row = blockIdx.x;
    int l = row & 1023;
    int b = row >> 14;
    int vl = vlens[b * 1024 + l];
    const float* s = scores + (long)row * 2048;
    int tid = threadIdx.x;

    float v[8], e2[8];
    float mu = -1e30f, mm = -1e30f;
    #pragma unroll
    for (int i = 0; i < 8; i++) {
        int kv = tid + (i << 8);
        v[i] = s[kv];
        mu = fmaxf(mu, v[i]);
        if (kv < vl) mm = fmaxf(mm, v[i]);
    }
    __shared__ float red[16];
    #pragma unroll
    for (int o = 16; o > 0; o >>= 1) {
        mu = fmaxf(mu, __shfl_xor_sync(0xffffffffu, mu, o));
        mm = fmaxf(mm, __shfl_xor_sync(0xffffffffu, mm, o));
    }
    int w = tid >> 5, lane = tid & 31;
    if (lane == 0) { red[w] = mu; red[w + 8] = mm; }
    __syncthreads();
    mu = -1e30f; mm = -1e30f;
    #pragma unroll
    for (int i = 0; i < 8; i++) { mu = fmaxf(mu, red[i]); mm = fmaxf(mm, red[8 + i]); }
    __syncthreads();

    float su = 0.f, sm = 0.f;
    #pragma unroll
    for (int i = 0; i < 8; i++) {
        int kv = tid + (i << 8);
        float eu = expf(v[i] - mu);
        float em = (kv < vl) ? expf(v[i] - mm) : 0.f;
        v[i] = eu; e2[i] = em;
        su += eu; sm += em;
    }
    #pragma unroll
    for (int o = 16; o > 0; o >>= 1) {
        su += __shfl_xor_sync(0xffffffffu, su, o);
        sm += __shfl_xor_sync(0xffffffffu, sm, o);
    }
    if (lane == 0) { red[w] = su; red[w + 8] = sm; }
    __syncthreads();
    su = 0.f; sm = 0.f;
    #pragma unroll
    for (int i = 0; i < 8; i++) { su += red[i]; sm += red[8 + i]; }
    float iu = 1.f / su, im = 1.f / sm;

    float* arow = attn + (long)row * 2048;
    bf16* hrow = ph_out + (long)row * 2048;
    bf16* lrow = pl_out + (long)row * 2048;
    #pragma unroll
    for (int i = 0; i < 8; i++) {
        int kv = tid + (i << 8);
        arow[kv] = v[i] * iu;
        float p = e2[i] * im;
        bf16 h = __float2bfloat16(p);
        hrow[kv] = h;
        lrow[kv] = __float2bfloat16(p - __bfloat162float(h));
    }
}

// ---------------------------------------------------------------------------
// Host launch
// ---------------------------------------------------------------------------
#define GSYM(p, s) cudaGetSymbolAddress((void**)&(p), s)

extern "C" void kernel_launch(void* const* d_in, const int* in_sizes, int n_in,
                              void* d_out, int out_size)
{
    const float* x        = (const float*)d_in[0];
    const float* z        = (const float*)d_in[1];
    const float* key_rope = (const float*)d_in[2];
    const int*   vlens    = (const int*)  d_in[3];
    const float* W_latent = (const float*)d_in[4];
    const float* W_q_down = (const float*)d_in[5];
    const float* b_q_down = (const float*)d_in[6];
    const float* W_q_up   = (const float*)d_in[7];
    const float* W_k_up   = (const float*)d_in[8];
    const float* W_v_up   = (const float*)d_in[9];
    const float* W_x_rope = (const float*)d_in[10];
    const float* W_k_rope = (const float*)d_in[11];
    const float* W_o      = (const float*)d_in[12];
    float* out = (float*)d_out;

    float *p_query, *p_qx, *p_qrope, *p_kx, *p_keyc, *p_value;
    bf16 *xh, *xl, *zh, *zl, *qlh, *qll, *qfh, *qfl, *kfh, *kfl,
         *vth, *vtl, *hoh, *hol, *pbh, *pbl;
    bf16 *WlatTh, *WlatTl, *WqdTh, *WqdTl, *WquTh, *WquTl, *WxrTh, *WxrTl,
         *WkuTh, *WkuTl, *WvuTh, *WvuTl, *WkrTh, *WkrTl, *WoTh, *WoTl;

    GSYM(p_query, g_query); GSYM(p_qx, g_qx); GSYM(p_qrope, g_qrope);
    GSYM(p_kx, g_kx); GSYM(p_keyc, g_keyc); GSYM(p_value, g_value);
    GSYM(xh, g_xh); GSYM(xl, g_xl); GSYM(zh, g_zallh); GSYM(zl, g_zalll);
    GSYM(qlh, g_qlath); GSYM(qll, g_qlatl);
    GSYM(qfh, g_qfh); GSYM(qfl, g_qfl); GSYM(kfh, g_kfh); GSYM(kfl, g_kfl);
    GSYM(vth, g_vth); GSYM(vtl, g_vtl); GSYM(hoh, g_hoh); GSYM(hol, g_hol);
    GSYM(pbh, g_pbh); GSYM(pbl, g_pbl);
    GSYM(WlatTh, g_WlatTh); GSYM(WlatTl, g_WlatTl);
    GSYM(WqdTh, g_WqdTh);   GSYM(WqdTl, g_WqdTl);
    GSYM(WquTh, g_WquTh);   GSYM(WquTl, g_WquTl);
    GSYM(WxrTh, g_WxrTh);   GSYM(WxrTl, g_WxrTl);
    GSYM(WkuTh, g_WkuTh);   GSYM(WkuTl, g_WkuTl);
    GSYM(WvuTh, g_WvuTh);   GSYM(WvuTl, g_WvuTl);
    GSYM(WkrTh, g_WkrTh);   GSYM(WkrTl, g_WkrTl);
    GSYM(WoTh, g_WoTh);     GSYM(WoTl, g_WoTl);

    const int SM128 = 66560;   // 2*(16K+16K) + 1K align pad
    const int SM64  = 50176;   // 2*(16K+8K)  + 1K align pad
    cudaFuncSetAttribute(gemm_tc<128>, cudaFuncAttributeMaxDynamicSharedMemorySize, SM128);
    cudaFuncSetAttribute(gemm_tc<64>,  cudaFuncAttributeMaxDynamicSharedMemorySize, SM64);
    dim3 tb(32, 8);

    // 1. concat copies
    copy_concat_kernel<<<8192, 256>>>(z,        out + OUT_ZALL);
    copy_concat_kernel<<<8192, 256>>>(key_rope, out + OUT_KRA);

    // 2. splits / weight transposes
    split_kernel<<<4096, 256>>>(x, xh, xl, 4194304L);
    transpose_split<<<dim3(32, 64, 1), tb>>>(W_latent, WlatTh, WlatTl, 2048, 1024, 0, 0);
    transpose_split<<<dim3(32, 64, 1), tb>>>(W_q_down, WqdTh,  WqdTl,  2048, 1024, 0, 0);
    transpose_split<<<dim3(32, 32, 1), tb>>>(W_q_up,   WquTh,  WquTl,  1024, 1024, 0, 0);
    transpose_split<<<dim3(32, 32, 1), tb>>>(W_x_rope, WxrTh,  WxrTl,  1024, 1024, 0, 0);
    transpose_split<<<dim3(32, 32, 1), tb>>>(W_k_up,   WkuTh,  WkuTl,  1024, 1024, 0, 0);
    transpose_split<<<dim3(32, 32, 1), tb>>>(W_v_up,   WvuTh,  WvuTl,  1024, 1024, 0, 0);
    transpose_split<<<dim3(32, 64, 1), tb>>>(W_k_rope, WkrTh,  WkrTl,  2048, 1024, 0, 0);
    transpose_split<<<dim3(64, 32, 1), tb>>>(W_o,      WoTh,   WoTl,   1024, 2048, 0, 0);

    // 3. z_all[:,1024:,:] = x @ W_latent
    gemm_tc<128><<<dim3(8, 8, 2), 256, SM128>>>(
        xh, xl, WlatTh, WlatTl, out + OUT_ZALL + 1024L * 1024, nullptr, nullptr, nullptr,
        2048, 2048, 2048, 1024,
        1, 1024L * 2048, 0, 0, 0, 2048L * 1024, 0, 1.f);
    split_kernel<<<4096, 256>>>(out + OUT_ZALL, zh, zl, 4194304L);

    // 4. q_lat = x @ W_q_down + b  (split output only)
    gemm_tc<128><<<dim3(8, 16, 1), 256, SM128>>>(
        xh, xl, WqdTh, WqdTl, nullptr, b_q_down, qlh, qll,
        2048, 2048, 2048, 1024, 1, 0, 0, 0, 0, 0, 0, 1.f);

    // 5. query / qx
    gemm_tc<128><<<dim3(8, 16, 1), 256, SM128>>>(
        qlh, qll, WquTh, WquTl, p_query, nullptr, nullptr, nullptr,
        1024, 1024, 1024, 1024, 1, 0, 0, 0, 0, 0, 0, 1.f);
    gemm_tc<128><<<dim3(8, 16, 1), 256, SM128>>>(
        qlh, qll, WxrTh, WxrTl, p_qx, nullptr, nullptr, nullptr,
        1024, 1024, 1024, 1024, 1, 0, 0, 0, 0, 0, 0, 1.f);

    // 6. key_c / value  (M=4096)
    gemm_tc<128><<<dim3(8, 32, 1), 256, SM128>>>(
        zh, zl, WkuTh, WkuTl, p_keyc, nullptr, nullptr, nullptr,
        1024, 1024, 1024, 1024, 1, 0, 0, 0, 0, 0, 0, 1.f);
    gemm_tc<128><<<dim3(8, 32, 1), 256, SM128>>>(
        zh, zl, WvuTh, WvuTl, p_value, nullptr, nullptr, nullptr,
        1024, 1024, 1024, 1024, 1, 0, 0, 0, 0, 0, 0, 1.f);

    // 7. kx = x @ W_k_rope
    gemm_tc<128><<<dim3(8, 16, 1), 256, SM128>>>(
        xh, xl, WkrTh, WkrTl, p_kx, nullptr, nullptr, nullptr,
        2048, 2048, 2048, 1024, 1, 0, 0, 0, 0, 0, 0, 1.f);

    // 8. rotary
    rotary_kernel<<<4096, 256>>>(p_qx, p_qrope, 0);
    rotary_kernel<<<4096, 256>>>(p_kx, out + OUT_KRA, 1);

    // 9. pack+split q/k
    pack_q_split<<<16384, 256>>>(p_query, p_qrope, qfh, qfl);
    pack_k_split<<<32768, 256>>>(p_keyc, out + OUT_KRA, kfh, kfl);

    // 10. value -> vt (transposed per batch)
    transpose_split<<<dim3(32, 64, 2), tb>>>(p_value, vth, vtl, 2048, 1024,
                                             2048L * 1024, 1024L * 2048);

    // 11. scores = Q @ K^T / sqrt(128)
    gemm_tc<128><<<dim3(16, 8, 32), 256, SM128>>>(
        qfh, qfl, kfh, kfl, out + OUT_SCORES, nullptr, nullptr, nullptr,
        128, 128, 128, 2048,
        1, 1024L * 128, 0, 2048L * 128, 0, 1024L * 2048, 0,
        0.08838834764831845f);

    // 12. dual softmax (probs as split bf16)
    softmax_kernel<<<32768, 256>>>(out + OUT_SCORES, vlens, out + OUT_ATTN, pbh, pbl);

    // 13. head_out = probs @ V  (split output)
    gemm_tc<64><<<dim3(1, 8, 32), 256, SM64>>>(
        pbh, pbl, vth, vtl, nullptr, nullptr, hoh, hol,
        2048, 2048, 2048, 1024,
        16, 16L * 1024 * 2048, 1024L * 2048,
        1024L * 2048, 64L * 2048,
        1024L * 1024, 64L,
        1.f);

    // 14. out = head_out @ W_o
    gemm_tc<128><<<dim3(16, 16, 1), 256, SM128>>>(
        hoh, hol, WoTh, WoTl, out + OUT_OUT, nullptr, nullptr, nullptr,
        1024, 1024, 1024, 2048, 1, 0, 0, 0, 0, 0, 0, 1.f);
}